// round 11
// baseline (speedup 1.0000x reference)
#include <cuda_runtime.h>
#include <cuda_bf16.h>
#include <math.h>

#define BB 64
#define TT 512
#define SS 512
#define NC 64
#define AT 128
#define NN 128
#define G4 2048
#define KT 64

// ---------------- persistent scratch (device globals; no allocation) ----------------
__device__ __align__(256) float g_psiT[(size_t)BB * AT * TT];  // [b][a][t] 16.8 MB
__device__ __align__(256) float g_h1[2][BB * SS];              // ping-pong
__device__ __align__(256) float g_h2[2][BB * SS];              // ping-pong
__device__ __align__(256) float g_c1[BB * SS];
__device__ __align__(256) float g_c2[BB * SS];
__device__ __align__(256) float g_ctx[BB * SS];
__device__ __align__(256) float g_bs0[G4];                     // bih0 + bhh0
__device__ __align__(256) float g_bs1[G4];                     // bih1 + bhh1

__device__ __forceinline__ float sigf(float v) { return 1.0f / (1.0f + expf(-v)); }

// ---------------- init: fused biases, ctx = h[:,0,:], zero states ----------------
__global__ void init_kernel(const float* __restrict__ h,
                            const float* __restrict__ bih0, const float* __restrict__ bhh0,
                            const float* __restrict__ bih1, const float* __restrict__ bhh1)
{
    int idx = blockIdx.x * blockDim.x + threadIdx.x;   // 0..32767
    if (idx < G4) {
        g_bs0[idx] = bih0[idx] + bhh0[idx];
        g_bs1[idx] = bih1[idx] + bhh1[idx];
    }
    if (idx < BB * SS) {
        int b = idx >> 9, d = idx & 511;
        g_ctx[idx] = h[(size_t)b * TT * SS + d];       // h[b, 0, d]
        g_h1[0][idx] = 0.f; g_h1[1][idx] = 0.f;
        g_h2[0][idx] = 0.f; g_h2[1][idx] = 0.f;
        g_c1[idx] = 0.f;    g_c2[idx] = 0.f;
    }
}

// ---------------- psi precompute (transposed): psiT[b][a][t] = h[b,t,:].Wpsi[a,:] + bpsi[a] ----
__global__ void __launch_bounds__(128) psi_kernel(const float* __restrict__ h,
                                                  const float* __restrict__ Wpsi,
                                                  const float* __restrict__ bpsi)
{
    __shared__ float4 s_hr[16][128];                   // 16 (b,t) rows x 512 floats
    const int tid = threadIdx.x;
    const int r0 = blockIdx.x * 16;
    #pragma unroll
    for (int i = 0; i < 16; i++) {
        int f = tid + 128 * i;                         // 0..2047 float4 slots
        int r = f >> 7, c = f & 127;
        s_hr[r][c] = ((const float4*)(h + (size_t)(r0 + r) * SS))[c];
    }
    __syncthreads();
    float acc[16];
    #pragma unroll
    for (int r = 0; r < 16; r++) acc[r] = 0.f;
    const float4* wr = (const float4*)(Wpsi + (size_t)tid * SS);
    for (int k = 0; k < 128; k++) {
        float4 w = wr[k];
        #pragma unroll
        for (int r = 0; r < 16; r++) {
            float4 v = s_hr[r][k];
            acc[r] += w.x * v.x + w.y * v.y + w.z * v.z + w.w * v.w;
        }
    }
    float bp = bpsi[tid];
    #pragma unroll
    for (int r = 0; r < 16; r++) {
        int row = r0 + r;
        int b = row >> 9, t = row & 511;
        g_psiT[((size_t)b * AT + tid) * TT + t] = acc[r] + bp;
    }
}

// ---------------- one K=512 accumulation phase of the fused GEMM ----------------
// Block tile: 32 gate-rows (4 gates x 8 d) x 32 batches. Thread: row rr, 4 batches (tb*4..+3).
// acc[j] holds packed (even-k, odd-k) partial sums -> f32x2 FMA, all operands 16B smem loads.
__device__ __forceinline__ void phase_accum(
    const float* __restrict__ act, const float* __restrict__ W,
    int ldw, int coff, int bx, int by, int tid, int rr, int tb,
    unsigned long long acc[4], float (*sW)[KT + 4], float (*sA)[KT + 4])
{
    float4 pw[2], pa[2];
    #pragma unroll
    for (int j = 0; j < 2; j++) {
        int u = tid + 256 * j;                 // 0..511
        int rl = u >> 4, k4 = u & 15;
        int gate = rl >> 3, dr = rl & 7;
        pw[j] = *(const float4*)(W + (size_t)(gate * 512 + bx * 8 + dr) * ldw + coff + k4 * 4);
        pa[j] = *(const float4*)(act + (size_t)(by * 32 + rl) * SS + k4 * 4);
    }
    for (int kc = 0; kc < SS; kc += KT) {
        #pragma unroll
        for (int j = 0; j < 2; j++) {
            int u = tid + 256 * j;
            int rl = u >> 4, k4 = u & 15;
            *(float4*)&sW[rl][k4 * 4] = pw[j];
            *(float4*)&sA[rl][k4 * 4] = pa[j];
        }
        __syncthreads();
        if (kc + KT < SS) {
            int kn = kc + KT;
            #pragma unroll
            for (int j = 0; j < 2; j++) {
                int u = tid + 256 * j;
                int rl = u >> 4, k4 = u & 15;
                int gate = rl >> 3, dr = rl & 7;
                pw[j] = *(const float4*)(W + (size_t)(gate * 512 + bx * 8 + dr) * ldw + coff + kn + k4 * 4);
                pa[j] = *(const float4*)(act + (size_t)(by * 32 + rl) * SS + kn + k4 * 4);
            }
        }
        const int b0 = tb * 4;
        #pragma unroll
        for (int k = 0; k < KT; k += 4) {
            ulonglong2 wv = *(const ulonglong2*)&sW[rr][k];      // (w_k,w_k+1),(w_k+2,w_k+3)
            #pragma unroll
            for (int j = 0; j < 4; j++) {
                ulonglong2 av = *(const ulonglong2*)&sA[b0 + j][k];
                asm("fma.rn.f32x2 %0, %1, %2, %0;" : "+l"(acc[j]) : "l"(av.x), "l"(wv.x));
                asm("fma.rn.f32x2 %0, %1, %2, %0;" : "+l"(acc[j]) : "l"(av.y), "l"(wv.y));
            }
        }
        __syncthreads();
    }
}

// ---------------- fused LSTM layer: GEMM (both K-sources) + bias + onehot + cell ----------------
// grid (64, 2) = (d-groups of 8, batch halves of 32), block 256.
// mode 0: g = [onehot|ctx].Wih0^T + h1.Whh0^T -> updates (h1,c1)
// mode 1: g = h1.Wih1^T + h2.Whh1^T           -> updates (h2,c2)
__global__ void __launch_bounds__(256) gemm_cell_kernel(int mode, int step, int par,
                                                        const int* __restrict__ x,
                                                        const float* __restrict__ WA, int lda, int coffa,
                                                        const float* __restrict__ WB,
                                                        const float* __restrict__ Wih0f)
{
    __shared__ __align__(16) float sW[32][KT + 4];
    __shared__ __align__(16) float sA[32][KT + 4];
    __shared__ float sG[4][8][33];

    const int tid = threadIdx.x;
    const int rr = tid & 31;       // row within block (gate = rr>>3, d-row = rr&7)
    const int tb = tid >> 5;       // 0..7 -> batches tb*4..tb*4+3
    const int bx = blockIdx.x, by = blockIdx.y;

    const float* actA; const float* actB; const float* bs; float* cb; float* hb;
    if (mode == 0) { actA = g_ctx;           actB = g_h1[par]; bs = g_bs0; cb = g_c1; hb = g_h1[par ^ 1]; }
    else           { actA = g_h1[par ^ 1];   actB = g_h2[par]; bs = g_bs1; cb = g_c2; hb = g_h2[par ^ 1]; }

    unsigned long long acc[4] = {0ull, 0ull, 0ull, 0ull};

    phase_accum(actA, WA, lda, coffa, bx, by, tid, rr, tb, acc, sW, sA);
    phase_accum(actB, WB, SS,  0,     bx, by, tid, rr, tb, acc, sW, sA);

    #pragma unroll
    for (int j = 0; j < 4; j++) {
        unsigned long long v = acc[j];
        float2 f = *reinterpret_cast<float2*>(&v);
        sG[rr >> 3][rr & 7][tb * 4 + j] = f.x + f.y;
    }
    __syncthreads();

    const int dd = tid & 7, bl = tid >> 3;     // 8 d x 32 b = 256 threads
    const int d = bx * 8 + dd;
    const int b = by * 32 + bl;

    float gi = sG[0][dd][bl] + bs[d];
    float gf = sG[1][dd][bl] + bs[d + 512];
    float gg = sG[2][dd][bl] + bs[d + 1024];
    float go = sG[3][dd][bl] + bs[d + 1536];

    if (mode == 0) {
        int col = x[b * NN + step];
        gi += Wih0f[(size_t)(d)        * 576 + col];
        gf += Wih0f[(size_t)(d + 512)  * 576 + col];
        gg += Wih0f[(size_t)(d + 1024) * 576 + col];
        go += Wih0f[(size_t)(d + 1536) * 576 + col];
    }

    const int idx = b * SS + d;
    float c = cb[idx];
    float cn = sigf(gf) * c + sigf(gi) * tanhf(gg);
    cb[idx] = cn;
    hb[idx] = sigf(go) * tanhf(cn);
}

// ---------------- fused attention + projection ----------------
// grid 64 (b), 512 threads. phi -> e -> softmax -> ctx -> p.
__global__ void __launch_bounds__(512) attn_kernel(const float* __restrict__ h,
                                                   const float* __restrict__ Wphi,
                                                   const float* __restrict__ bphi,
                                                   const float* __restrict__ Wcd,
                                                   const float* __restrict__ bcd,
                                                   float* __restrict__ out, int step, int par)
{
    __shared__ __align__(16) float s_h2[SS];
    __shared__ __align__(16) float s_ctx[SS];
    __shared__ float s_phi[AT];
    __shared__ float s_alpha[TT];
    __shared__ float s_red[32];

    const int b = blockIdx.x, tid = threadIdx.x;
    const int lane = tid & 31, wid = tid >> 5;

    s_h2[tid] = g_h2[par ^ 1][b * SS + tid];
    __syncthreads();

    // phi_s[a] = h2[b,:] . Wphi[a,:] + bphi[a]
    if (tid < AT) {
        const float4* wr = (const float4*)(Wphi + (size_t)tid * SS);
        const float4* hh = (const float4*)s_h2;
        float a = 0.f;
        #pragma unroll 4
        for (int k = 0; k < 128; k++) {
            float4 w = wr[k], v = hh[k];
            a += w.x * v.x + w.y * v.y + w.z * v.z + w.w * v.w;
        }
        s_phi[tid] = a + bphi[tid];
    }
    __syncthreads();

    // e[t] = phi . psiT[b][:][t]   (coalesced over t = tid)
    const float* prow = g_psiT + (size_t)b * AT * TT + tid;
    float e = 0.f;
    #pragma unroll 8
    for (int a = 0; a < AT; a++) e += s_phi[a] * prow[(size_t)a * TT];

    // block softmax over t (512)
    float m = e;
    #pragma unroll
    for (int off = 16; off; off >>= 1) m = fmaxf(m, __shfl_xor_sync(0xffffffffu, m, off));
    if (lane == 0) s_red[wid] = m;
    __syncthreads();
    if (wid == 0) {
        float v = (lane < 16) ? s_red[lane] : -1e30f;
        #pragma unroll
        for (int off = 8; off; off >>= 1) v = fmaxf(v, __shfl_xor_sync(0xffffffffu, v, off));
        if (lane == 0) s_red[0] = v;
    }
    __syncthreads();
    float M = s_red[0];
    float ex = expf(e - M);
    __syncthreads();
    float ssum = ex;
    #pragma unroll
    for (int off = 16; off; off >>= 1) ssum += __shfl_xor_sync(0xffffffffu, ssum, off);
    if (lane == 0) s_red[wid] = ssum;
    __syncthreads();
    if (wid == 0) {
        float v = (lane < 16) ? s_red[lane] : 0.f;
        #pragma unroll
        for (int off = 8; off; off >>= 1) v += __shfl_xor_sync(0xffffffffu, v, off);
        if (lane == 0) s_red[0] = v;
    }
    __syncthreads();
    s_alpha[tid] = ex / s_red[0];
    __syncthreads();

    // ctx[d] = sum_t alpha[t] * h[b,t,d]   (coalesced over d = tid)
    const float* hb = h + (size_t)b * TT * SS + tid;
    float acc = 0.f;
    #pragma unroll 8
    for (int t = 0; t < TT; t++) acc += s_alpha[t] * hb[(size_t)t * SS];
    s_ctx[tid] = acc;
    g_ctx[b * SS + tid] = acc;
    __syncthreads();

    // p[c] = concat(h2, ctx) . Wcd[c,:] + bcd[c]; 4 partial threads per class
    if (tid < 256) {
        int c = tid >> 2, part = tid & 3;
        const float4* wv = (const float4*)(Wcd + (size_t)c * 1024) + part * 64;
        const float4* src = (part < 2) ? ((const float4*)s_h2 + (part & 1) * 64)
                                       : ((const float4*)s_ctx + (part & 1) * 64);
        float p = 0.f;
        #pragma unroll 4
        for (int j = 0; j < 64; j++) {
            float4 w = wv[j], v = src[j];
            p += w.x * v.x + w.y * v.y + w.z * v.z + w.w * v.w;
        }
        p += __shfl_xor_sync(0xffffffffu, p, 1);
        p += __shfl_xor_sync(0xffffffffu, p, 2);
        if (part == 0)
            out[((size_t)b * NN + step) * NC + c] = p + bcd[c];
    }
}

// ---------------- host launcher ----------------
extern "C" void kernel_launch(void* const* d_in, const int* in_sizes, int n_in,
                              void* d_out, int out_size)
{
    const int*   x    = (const int*)  d_in[0];
    const float* h    = (const float*)d_in[1];
    const float* Wih0 = (const float*)d_in[2];
    const float* Whh0 = (const float*)d_in[3];
    const float* bih0 = (const float*)d_in[4];
    const float* bhh0 = (const float*)d_in[5];
    const float* Wih1 = (const float*)d_in[6];
    const float* Whh1 = (const float*)d_in[7];
    const float* bih1 = (const float*)d_in[8];
    const float* bhh1 = (const float*)d_in[9];
    const float* Wphi = (const float*)d_in[10];
    const float* bphi = (const float*)d_in[11];
    const float* Wpsi = (const float*)d_in[12];
    const float* bpsi = (const float*)d_in[13];
    const float* Wcd  = (const float*)d_in[14];
    const float* bcd  = (const float*)d_in[15];
    float* out = (float*)d_out;

    init_kernel<<<128, 256>>>(h, bih0, bhh0, bih1, bhh1);
    psi_kernel<<<(BB * TT) / 16, 128>>>(h, Wpsi, bpsi);

    dim3 ggrid(64, 2);
    for (int s = 0; s < NN; s++) {
        int par = s & 1;
        gemm_cell_kernel<<<ggrid, 256>>>(0, s, par, x, Wih0, 576, 64, Whh0, Wih0);
        gemm_cell_kernel<<<ggrid, 256>>>(1, s, par, x, Wih1, 512, 0,  Whh1, Wih0);
        attn_kernel<<<BB, 512>>>(h, Wphi, bphi, Wcd, bcd, out, s, par);
    }
}

// round 15
// speedup vs baseline: 1.6125x; 1.6125x over previous
#include <cuda_runtime.h>
#include <cuda_bf16.h>
#include <math.h>

#define BB 64
#define TT 512
#define SS 512
#define NC 64
#define AT 128
#define NN 128
#define NBLK 128
#define NTHR 256

// ---------------- persistent scratch (device globals; no allocation) ----------------
__device__ __align__(256) float g_psiT[(size_t)BB * AT * TT];  // [b][a][t] 16.8 MB
__device__ __align__(256) float g_h1[2][BB * SS];
__device__ __align__(256) float g_h2[2][BB * SS];
__device__ __align__(256) float g_ctx[2][BB * SS];
__device__ unsigned g_bar_count = 0;
__device__ unsigned g_bar_gen = 0;

__device__ __forceinline__ float sigf(float v) { return 1.0f / (1.0f + expf(-v)); }

// ---------------- smem layout (floats) ----------------
#define OFF_W0   0            // 16 x 1028
#define OFF_W1   16448        // 16 x 1028
#define OFF_E    32896        // 16 x 64   (Wih0 one-hot cols, block's rows)
#define OFF_WCD  33920        // 1024      (blocks 64..127: Wcd row)
#define OFF_B0   34944        // 16
#define OFF_B1   34960        // 16
#define OFF_ACT  34976        // 2 x (64 x 68)
#define OFF_G    43680        // 16 x 68
#define OFF_H2S  44768        // 512
#define OFF_PHI  45280        // 128
#define OFF_EX   45408        // 512
#define OFF_RED  45920        // 32
#define SMEM_FLOATS 45952
#define SMEM_BYTES (SMEM_FLOATS * 4)   // 183808

// ---------------- grid barrier (all 128 blocks co-resident) ----------------
__device__ __forceinline__ void grid_barrier() {
    __syncthreads();
    if (threadIdx.x == 0) {
        unsigned old = *(volatile unsigned*)&g_bar_gen;
        __threadfence();
        unsigned t = atomicAdd(&g_bar_count, 1u);
        if (t == NBLK - 1) {
            g_bar_count = 0;
            __threadfence();
            *(volatile unsigned*)&g_bar_gen = old + 1;
        } else {
            while (*(volatile unsigned*)&g_bar_gen == old) __nanosleep(64);
        }
        __threadfence();
    }
    __syncthreads();
}

__device__ __forceinline__ void cp16(float* sp, const float* gp) {
    unsigned s = (unsigned)__cvta_generic_to_shared(sp);
    asm volatile("cp.async.cg.shared.global [%0], [%1], 16;" :: "r"(s), "l"(gp));
}

// stage one [64 b][64 k] act chunk into smem buffer via cp.async
__device__ __forceinline__ void stage_chunk(float* buf, const float* actA, const float* actB,
                                            int kc, int tid) {
    #pragma unroll
    for (int i = 0; i < 4; i++) {
        int u = tid + 256 * i;             // 0..1023
        int b = u >> 4, k4 = (u & 15) * 4;
        const float* src = (kc < 512) ? (actA + b * SS + kc + k4)
                                      : (actB + b * SS + (kc - 512) + k4);
        cp16(buf + b * 68 + k4, src);
    }
    asm volatile("cp.async.commit_group;");
}

// ---------------- one LSTM layer: GEMM over K=1024 (two sources) + cell ----------------
// block tile: 16 gate-rows (4 gates x 4 d, d = bid*4 + dr) x 64 batches.
// thread (GEMM): rr = tid&15 row, 4 batches; acc = f32x2 pairs over k.
template <bool ONEHOT>
__device__ void lstm_phase(float* sm, const float* sW, const float* sB,
                           const float* actA, const float* actB,
                           float* hout, float& c_reg,
                           const int* xin, int step, int bid, int tid)
{
    float* sAct = sm + OFF_ACT;
    float* sG   = sm + OFF_G;

    stage_chunk(sAct, actA, actB, 0, tid);

    const int rr = tid & 15, b0 = (tid >> 4) * 4;
    unsigned long long acc[4] = {0ull, 0ull, 0ull, 0ull};

    for (int c = 0; c < 16; c++) {
        if (c < 15) {
            stage_chunk(sAct + ((c + 1) & 1) * 4352, actA, actB, (c + 1) * 64, tid);
            asm volatile("cp.async.wait_group 1;");
        } else {
            asm volatile("cp.async.wait_group 0;");
        }
        __syncthreads();

        const float* wrow = sW + rr * 1028 + c * 64;
        const float* ab   = sAct + (c & 1) * 4352;
        #pragma unroll
        for (int k = 0; k < 64; k += 4) {
            ulonglong2 wv = *(const ulonglong2*)(wrow + k);
            #pragma unroll
            for (int j = 0; j < 4; j++) {
                ulonglong2 av = *(const ulonglong2*)(ab + (b0 + j) * 68 + k);
                asm("fma.rn.f32x2 %0, %1, %2, %0;" : "+l"(acc[j]) : "l"(av.x), "l"(wv.x));
                asm("fma.rn.f32x2 %0, %1, %2, %0;" : "+l"(acc[j]) : "l"(av.y), "l"(wv.y));
            }
        }
        __syncthreads();
    }

    #pragma unroll
    for (int j = 0; j < 4; j++) {
        unsigned long long v = acc[j];
        float2 f = *reinterpret_cast<float2*>(&v);
        sG[rr * 68 + b0 + j] = f.x + f.y;
    }
    __syncthreads();

    // cell epilogue: thread = (dd = tid>>6 in 0..3, b = tid&63)
    const int dd = tid >> 6, b = tid & 63;
    float gi = sG[(dd)      * 68 + b] + sB[dd];
    float gf = sG[(4 + dd)  * 68 + b] + sB[4 + dd];
    float gg = sG[(8 + dd)  * 68 + b] + sB[8 + dd];
    float go = sG[(12 + dd) * 68 + b] + sB[12 + dd];
    if (ONEHOT) {
        int col = xin[b * NN + step];
        gi += sm[OFF_E + (dd)      * 64 + col];
        gf += sm[OFF_E + (4 + dd)  * 64 + col];
        gg += sm[OFF_E + (8 + dd)  * 64 + col];
        go += sm[OFF_E + (12 + dd) * 64 + col];
    }
    float cn = sigf(gf) * c_reg + sigf(gi) * tanhf(gg);
    c_reg = cn;
    hout[b * SS + bid * 4 + dd] = sigf(go) * tanhf(cn);
}

// ---------------- attention (blocks 0..63, b = bid) ----------------
__device__ void attn_phase(float* sm, const float* h, const float* Wphi, const float* bphi,
                           int parN, int bid, int tid)
{
    const int b = bid, lane = tid & 31, wid = tid >> 5;
    float* s_red = sm + OFF_RED;

    sm[OFF_H2S + tid]       = g_h2[parN][b * SS + tid];
    sm[OFF_H2S + 256 + tid] = g_h2[parN][b * SS + 256 + tid];
    __syncthreads();

    // phi: thread pair per a
    {
        int a = tid >> 1, half = tid & 1;
        const float4* w4 = (const float4*)(Wphi + (size_t)a * SS) + half * 64;
        const float4* h4 = (const float4*)(sm + OFF_H2S) + half * 64;
        float p = 0.f;
        #pragma unroll 8
        for (int i = 0; i < 64; i++) {
            float4 w = w4[i], v = h4[i];
            p += w.x * v.x + w.y * v.y + w.z * v.z + w.w * v.w;
        }
        p += __shfl_xor_sync(0xffffffffu, p, 1);
        if (!half) sm[OFF_PHI + a] = p + bphi[a];
    }
    __syncthreads();

    // e for t0 = tid, t1 = tid + 256
    const float* pT = g_psiT + (size_t)b * AT * TT;
    float e0 = 0.f, e1 = 0.f;
    #pragma unroll 8
    for (int a = 0; a < AT; a++) {
        float ph = sm[OFF_PHI + a];
        e0 += ph * pT[(size_t)a * TT + tid];
        e1 += ph * pT[(size_t)a * TT + 256 + tid];
    }

    // block max
    float m = fmaxf(e0, e1);
    #pragma unroll
    for (int off = 16; off; off >>= 1) m = fmaxf(m, __shfl_xor_sync(0xffffffffu, m, off));
    if (lane == 0) s_red[wid] = m;
    __syncthreads();
    if (tid < 32) {
        float v = (lane < 8) ? s_red[lane] : -1e30f;
        #pragma unroll
        for (int off = 4; off; off >>= 1) v = fmaxf(v, __shfl_xor_sync(0xffffffffu, v, off));
        if (lane == 0) s_red[0] = v;
    }
    __syncthreads();
    float M = s_red[0];
    __syncthreads();

    float x0 = expf(e0 - M), x1 = expf(e1 - M);
    sm[OFF_EX + tid] = x0;
    sm[OFF_EX + 256 + tid] = x1;
    float s = x0 + x1;
    #pragma unroll
    for (int off = 16; off; off >>= 1) s += __shfl_xor_sync(0xffffffffu, s, off);
    if (lane == 0) s_red[wid] = s;
    __syncthreads();
    if (tid < 32) {
        float v = (lane < 8) ? s_red[lane] : 0.f;
        #pragma unroll
        for (int off = 4; off; off >>= 1) v += __shfl_xor_sync(0xffffffffu, v, off);
        if (lane == 0) s_red[0] = v;
    }
    __syncthreads();
    float invS = 1.0f / s_red[0];

    // ctx[d pair] = invS * sum_t ex[t] * h[b][t][d]
    const float* hb = h + (size_t)b * TT * SS + 2 * tid;
    float cx = 0.f, cy = 0.f;
    #pragma unroll 8
    for (int t = 0; t < TT; t++) {
        float al = sm[OFF_EX + t];
        float2 hv = *(const float2*)(hb + (size_t)t * SS);
        cx += al * hv.x; cy += al * hv.y;
    }
    float2 o; o.x = cx * invS; o.y = cy * invS;
    *(float2*)(g_ctx[parN] + b * SS + 2 * tid) = o;
}

// ---------------- class projection for step s_done (blocks 64..127, c = bid-64) ----------------
__device__ void proj_phase(float* sm, int s_done, float bcd_c, float* out, int bid, int tid)
{
    int par = (s_done + 1) & 1;     // buffers written at step s_done
    const float* h2r = g_h2[par];
    const float* ctr = g_ctx[par];
    int c = bid - 64;
    int b = tid >> 2, p = tid & 3;
    const float* src = ((p < 2) ? h2r : ctr) + b * SS + (p & 1) * 256;
    const float* w = sm + OFF_WCD + (p >> 1) * 512 + (p & 1) * 256;
    float acc = 0.f;
    #pragma unroll 8
    for (int i = 0; i < 64; i++) {
        float4 sv = *(const float4*)(src + 4 * i);
        float4 wv = *(const float4*)(w + 4 * i);
        acc += sv.x * wv.x + sv.y * wv.y + sv.z * wv.z + sv.w * wv.w;
    }
    acc += __shfl_xor_sync(0xffffffffu, acc, 1);
    acc += __shfl_xor_sync(0xffffffffu, acc, 2);
    if (p == 0)
        out[((size_t)b * NN + s_done) * NC + c] = acc + bcd_c;
}

// ---------------- init: ctx = h[:,0,:], zero states ----------------
__global__ void init_kernel(const float* __restrict__ h)
{
    int idx = blockIdx.x * blockDim.x + threadIdx.x;   // 0..32767
    if (idx < BB * SS) {
        int b = idx >> 9, d = idx & 511;
        g_ctx[0][idx] = h[(size_t)b * TT * SS + d];
        g_h1[0][idx] = 0.f;
        g_h2[0][idx] = 0.f;
    }
}

// ---------------- psi precompute (transposed) ----------------
__global__ void __launch_bounds__(128) psi_kernel(const float* __restrict__ h,
                                                  const float* __restrict__ Wpsi,
                                                  const float* __restrict__ bpsi)
{
    __shared__ float4 s_hr[16][128];
    const int tid = threadIdx.x;
    const int r0 = blockIdx.x * 16;
    #pragma unroll
    for (int i = 0; i < 16; i++) {
        int f = tid + 128 * i;
        int r = f >> 7, c = f & 127;
        s_hr[r][c] = ((const float4*)(h + (size_t)(r0 + r) * SS))[c];
    }
    __syncthreads();
    float acc[16];
    #pragma unroll
    for (int r = 0; r < 16; r++) acc[r] = 0.f;
    const float4* wr = (const float4*)(Wpsi + (size_t)tid * SS);
    for (int k = 0; k < 128; k++) {
        float4 w = wr[k];
        #pragma unroll
        for (int r = 0; r < 16; r++) {
            float4 v = s_hr[r][k];
            acc[r] += w.x * v.x + w.y * v.y + w.z * v.z + w.w * v.w;
        }
    }
    float bp = bpsi[tid];
    #pragma unroll
    for (int r = 0; r < 16; r++) {
        int row = r0 + r;
        int b = row >> 9, t = row & 511;
        g_psiT[((size_t)b * AT + tid) * TT + t] = acc[r] + bp;
    }
}

// ---------------- the persistent kernel ----------------
__global__ void __launch_bounds__(NTHR, 1) speller_persistent(
    const int* __restrict__ xin, const float* __restrict__ h,
    const float* __restrict__ Wih0, const float* __restrict__ Whh0,
    const float* __restrict__ bih0, const float* __restrict__ bhh0,
    const float* __restrict__ Wih1, const float* __restrict__ Whh1,
    const float* __restrict__ bih1, const float* __restrict__ bhh1,
    const float* __restrict__ Wphi, const float* __restrict__ bphi,
    const float* __restrict__ Wcd,  const float* __restrict__ bcd,
    float* __restrict__ out)
{
    extern __shared__ float sm[];
    const int bid = blockIdx.x, tid = threadIdx.x;

    // ---- load block-resident weights into smem (once) ----
    // rows: rr = g*4 + dr -> row = g*512 + bid*4 + dr
    for (int idx = tid; idx < 16 * 512; idx += NTHR) {
        int rr = idx >> 9, k = idx & 511;
        int row = (rr >> 2) * 512 + bid * 4 + (rr & 3);
        sm[OFF_W0 + rr * 1028 + k]       = Wih0[(size_t)row * 576 + 64 + k];
        sm[OFF_W0 + rr * 1028 + 512 + k] = Whh0[(size_t)row * 512 + k];
        sm[OFF_W1 + rr * 1028 + k]       = Wih1[(size_t)row * 512 + k];
        sm[OFF_W1 + rr * 1028 + 512 + k] = Whh1[(size_t)row * 512 + k];
    }
    for (int idx = tid; idx < 16 * 64; idx += NTHR) {
        int rr = idx >> 6, cc = idx & 63;
        int row = (rr >> 2) * 512 + bid * 4 + (rr & 3);
        sm[OFF_E + idx] = Wih0[(size_t)row * 576 + cc];
    }
    if (bid >= 64) {
        int c = bid - 64;
        for (int k = tid; k < 1024; k += NTHR)
            sm[OFF_WCD + k] = Wcd[(size_t)c * 1024 + k];
    }
    if (tid < 16) {
        int row = (tid >> 2) * 512 + bid * 4 + (tid & 3);
        sm[OFF_B0 + tid] = bih0[row] + bhh0[row];
        sm[OFF_B1 + tid] = bih1[row] + bhh1[row];
    }
    float bcd_c = (bid >= 64) ? bcd[bid - 64] : 0.f;
    float c1 = 0.f, c2 = 0.f;
    __syncthreads();

    for (int s = 0; s < NN; s++) {
        int par = s & 1;
        lstm_phase<true>(sm, sm + OFF_W0, sm + OFF_B0,
                         g_ctx[par], g_h1[par], g_h1[par ^ 1], c1, xin, s, bid, tid);
        grid_barrier();
        lstm_phase<false>(sm, sm + OFF_W1, sm + OFF_B1,
                          g_h1[par ^ 1], g_h2[par], g_h2[par ^ 1], c2, xin, s, bid, tid);
        grid_barrier();
        if (bid < 64)      attn_phase(sm, h, Wphi, bphi, par ^ 1, bid, tid);
        else if (s > 0)    proj_phase(sm, s - 1, bcd_c, out, bid, tid);
        grid_barrier();
    }
    if (bid >= 64) proj_phase(sm, NN - 1, bcd_c, out, bid, tid);
}

// ---------------- host launcher ----------------
extern "C" void kernel_launch(void* const* d_in, const int* in_sizes, int n_in,
                              void* d_out, int out_size)
{
    const int*   x    = (const int*)  d_in[0];
    const float* h    = (const float*)d_in[1];
    const float* Wih0 = (const float*)d_in[2];
    const float* Whh0 = (const float*)d_in[3];
    const float* bih0 = (const float*)d_in[4];
    const float* bhh0 = (const float*)d_in[5];
    const float* Wih1 = (const float*)d_in[6];
    const float* Whh1 = (const float*)d_in[7];
    const float* bih1 = (const float*)d_in[8];
    const float* bhh1 = (const float*)d_in[9];
    const float* Wphi = (const float*)d_in[10];
    const float* bphi = (const float*)d_in[11];
    const float* Wpsi = (const float*)d_in[12];
    const float* bpsi = (const float*)d_in[13];
    const float* Wcd  = (const float*)d_in[14];
    const float* bcd  = (const float*)d_in[15];
    float* out = (float*)d_out;

    cudaFuncSetAttribute(speller_persistent,
                         cudaFuncAttributeMaxDynamicSharedMemorySize, SMEM_BYTES);

    init_kernel<<<128, 256>>>(h);
    psi_kernel<<<(BB * TT) / 16, 128>>>(h, Wpsi, bpsi);
    speller_persistent<<<NBLK, NTHR, SMEM_BYTES>>>(
        x, h, Wih0, Whh0, bih0, bhh0, Wih1, Whh1, bih1, bhh1,
        Wphi, bphi, Wcd, bcd, out);
}